// round 1
// baseline (speedup 1.0000x reference)
#include <cuda_runtime.h>
#include <cstdint>

#define BB 8
#define CC 64
#define HH 128
#define WW 128
#define HW (HH*WW)
#define KT 9     // taps
#define OC 27    // offset conv output channels
#define CO 64    // dcn output channels
#define CK 576   // C*K

// scratch: sample coords + mask, [B][9][H][W]
__device__ float g_py[BB*KT*HW];
__device__ float g_px[BB*KT*HW];
__device__ float g_m [BB*KT*HW];

// ---------------------------------------------------------------------------
// Kernel 1: offset conv (3x3, pad1, stride1) -> py, px, m (sigmoid applied)
// one thread per (b,h,w); weights staged in smem padded to 28 for float4 LDS
// ---------------------------------------------------------------------------
#define K1_SMEM (CK*28*4)   // 576 * 28 floats = 64512 B

__global__ void __launch_bounds__(256) offset_conv_kernel(
    const float* __restrict__ x,
    const float* __restrict__ wofs,
    const float* __restrict__ bofs)
{
    extern __shared__ float s_w[];   // [c*9+t][28]
    const int tid = threadIdx.x;

    // stage weights: s_w[pos*28 + oc] = wofs[oc*576 + pos], oc==27 -> 0
    for (int i = tid; i < CK*28; i += 256) {
        int pos = i / 28, oc = i % 28;
        s_w[i] = (oc < OC) ? __ldg(&wofs[oc*CK + pos]) : 0.f;
    }
    __syncthreads();

    const int gid = blockIdx.x * 256 + tid;
    const int ww = gid & (WW-1);
    const int hh = (gid >> 7) & (HH-1);
    const int b  = gid >> 14;

    float acc[28];
#pragma unroll
    for (int oc = 0; oc < 28; oc++) acc[oc] = (oc < OC) ? __ldg(&bofs[oc]) : 0.f;

    const float* xb = x + (size_t)b * CC * HW;

    for (int c = 0; c < CC; c++) {
        const float* xc = xb + c * HW;
#pragma unroll
        for (int t = 0; t < 9; t++) {
            const int dy = t / 3 - 1, dx = t % 3 - 1;
            const int yy = hh + dy, xx = ww + dx;
            float xv = 0.f;
            if (yy >= 0 && yy < HH && xx >= 0 && xx < WW) xv = __ldg(&xc[yy*WW + xx]);
            const float4* wv = (const float4*)(s_w + (c*9 + t) * 28);
#pragma unroll
            for (int q = 0; q < 7; q++) {
                float4 a = wv[q];
                acc[q*4+0] += xv * a.x;
                acc[q*4+1] += xv * a.y;
                acc[q*4+2] += xv * a.z;
                acc[q*4+3] += xv * a.w;
            }
        }
    }

    // epilogue: py = oy + (h-1) + k/3 ; px = ox + (w-1) + k%3 ; m = sigmoid
#pragma unroll
    for (int k = 0; k < KT; k++) {
        const float py = acc[k]      + (float)(hh - 1 + k / 3);
        const float px = acc[9 + k]  + (float)(ww - 1 + k % 3);
        const float z  = acc[18 + k];
        const float mv = 1.f / (1.f + __expf(-z));
        const int o = ((b*KT + k) * HH + hh) * WW + ww;
        g_py[o] = py; g_px[o] = px; g_m[o] = mv;
    }
}

// ---------------------------------------------------------------------------
// Kernel 2: fused bilinear gather + per-pixel GEMM
// block = 32 pixels (one row chunk), blockDim (32,8)
// smem: col[576][32] | wd chunk [64][68] (transposed, padded) | prepass w4/i4
// ---------------------------------------------------------------------------
#define SC_COL 0                        // 576*32 floats
#define SC_WD  (CK*32)                  // + 64*68 floats
#define SC_W4  (SC_WD + 64*68)          // + 9*32*4 floats
#define SC_I4  (SC_W4 + KT*32*4)        // + 9*32*4 ints
#define K2_FLOATS (SC_I4 + KT*32*4)
#define K2_SMEM (K2_FLOATS*4)           // 100352 B

__global__ void __launch_bounds__(256) dcn_gemm_kernel(
    const float* __restrict__ x,
    const float* __restrict__ wdcn,
    const float* __restrict__ bdcn,
    float* __restrict__ out)
{
    extern __shared__ float smem[];
    float* s_col = smem + SC_COL;
    float* s_wd  = smem + SC_WD;
    float* s_w4  = smem + SC_W4;
    int*   s_i4  = (int*)(smem + SC_I4);

    const int tx = threadIdx.x;          // pixel in tile (0..31)
    const int ty = threadIdx.y;          // 0..7
    const int t  = ty * 32 + tx;

    const int b    = blockIdx.x >> 9;    // 512 tiles per batch
    const int tile = blockIdx.x & 511;
    const int pix0 = tile * 32;
    const int row  = pix0 >> 7;
    const int col0 = pix0 & 127;

    // ---- prepass: per (k, px) corner weights (mask folded) + clamped indices
    for (int it = t; it < KT*32; it += 256) {
        const int k = it >> 5, px = it & 31;
        const int o = ((b*KT + k) * HH + row) * WW + (col0 + px);
        const float py = g_py[o], pxx = g_px[o], mv = g_m[o];
        const float y0f = floorf(py), x0f = floorf(pxx);
        const float dy = py - y0f, dx = pxx - x0f;
        const int y0 = (int)y0f, x0 = (int)x0f;
        const int y1 = y0 + 1,  x1 = x0 + 1;

        const bool vy0 = (y0 >= 0) & (y0 < HH);
        const bool vy1 = (y1 >= 0) & (y1 < HH);
        const bool vx0 = (x0 >= 0) & (x0 < WW);
        const bool vx1 = (x1 >= 0) & (x1 < WW);
        const int cy0 = min(max(y0, 0), HH-1), cy1 = min(max(y1, 0), HH-1);
        const int cx0 = min(max(x0, 0), WW-1), cx1 = min(max(x1, 0), WW-1);

        float4 wq;
        wq.x = (1.f-dy)*(1.f-dx)*mv * (float)(vy0 & vx0);
        wq.y = (1.f-dy)*dx      *mv * (float)(vy0 & vx1);
        wq.z = dy*(1.f-dx)      *mv * (float)(vy1 & vx0);
        wq.w = dy*dx            *mv * (float)(vy1 & vx1);
        int4 iq;
        iq.x = cy0*WW + cx0;  iq.y = cy0*WW + cx1;
        iq.z = cy1*WW + cx0;  iq.w = cy1*WW + cx1;

        *(float4*)(s_w4 + it*4) = wq;
        *(int4*)  (s_i4 + it*4) = iq;
    }
    __syncthreads();

    // ---- gather: col[c*9+k][px]
    for (int c0 = 0; c0 < CC; c0 += 8) {
        const int cc = c0 + ty;
        const float* xc = x + ((size_t)(b*CC + cc)) * HW;
#pragma unroll
        for (int k = 0; k < KT; k++) {
            const int base = (k*32 + tx) * 4;
            const float4 wq = *(const float4*)(s_w4 + base);
            const int4   iq = *(const int4*)  (s_i4 + base);
            float v = wq.x * __ldg(&xc[iq.x])
                    + wq.y * __ldg(&xc[iq.y])
                    + wq.z * __ldg(&xc[iq.z])
                    + wq.w * __ldg(&xc[iq.w]);
            s_col[(cc*9 + k) * 32 + tx] = v;
        }
    }
    __syncthreads();

    // ---- GEMM: out[co][px] = sum_ck wd[co][ck] * col[ck][px]
    float acc[8];
#pragma unroll
    for (int j = 0; j < 8; j++) acc[j] = 0.f;

    for (int chunk = 0; chunk < 9; chunk++) {
        // stage transposed weight chunk: s_wd[kk*68 + co] = wd[co*576 + chunk*64 + kk]
        for (int i = t; i < 64*64; i += 256) {
            const int co = i >> 6, kk = i & 63;
            s_wd[kk*68 + co] = __ldg(&wdcn[co*CK + chunk*64 + kk]);
        }
        __syncthreads();
#pragma unroll
        for (int kk = 0; kk < 64; kk++) {
            const float cv = s_col[(chunk*64 + kk) * 32 + tx];
            const float4* wv = (const float4*)(s_wd + kk*68 + ty*8);
            const float4 w0 = wv[0], w1 = wv[1];
            acc[0] += cv * w0.x;  acc[1] += cv * w0.y;
            acc[2] += cv * w0.z;  acc[3] += cv * w0.w;
            acc[4] += cv * w1.x;  acc[5] += cv * w1.y;
            acc[6] += cv * w1.z;  acc[7] += cv * w1.w;
        }
        __syncthreads();
    }

    // ---- epilogue
#pragma unroll
    for (int j = 0; j < 8; j++) {
        const int co = ty*8 + j;
        out[((size_t)(b*CO + co)) * HW + row*WW + col0 + tx] = acc[j] + __ldg(&bdcn[co]);
    }
}

// ---------------------------------------------------------------------------
extern "C" void kernel_launch(void* const* d_in, const int* in_sizes, int n_in,
                              void* d_out, int out_size)
{
    const float* x        = (const float*)d_in[0];
    const float* w_offset = (const float*)d_in[1];
    const float* b_offset = (const float*)d_in[2];
    const float* w_dcn    = (const float*)d_in[3];
    const float* b_dcn    = (const float*)d_in[4];
    float* out = (float*)d_out;

    cudaFuncSetAttribute(offset_conv_kernel,
                         cudaFuncAttributeMaxDynamicSharedMemorySize, K1_SMEM);
    cudaFuncSetAttribute(dcn_gemm_kernel,
                         cudaFuncAttributeMaxDynamicSharedMemorySize, K2_SMEM);

    offset_conv_kernel<<<(BB*HW)/256, 256, K1_SMEM>>>(x, w_offset, b_offset);
    dcn_gemm_kernel<<<BB*(HW/32), dim3(32,8), K2_SMEM>>>(x, w_dcn, b_dcn, out);
}

// round 2
// speedup vs baseline: 1.4129x; 1.4129x over previous
#include <cuda_runtime.h>
#include <cstdint>

#define BB 8
#define CC 64
#define HH 128
#define WW 128
#define HW (HH*WW)
#define KT 9     // taps
#define OC 27    // offset conv output channels
#define CO 64    // dcn output channels
#define CK 576   // C*K

// scratch: sample coords + mask, [B][9][H][W]
__device__ float g_py[BB*KT*HW];
__device__ float g_px[BB*KT*HW];
__device__ float g_m [BB*KT*HW];

// ---------------------------------------------------------------------------
// Kernel 1: offset conv (3x3, pad1, stride1) -> py, px, m (sigmoid applied)
// ---------------------------------------------------------------------------
#define K1_SMEM (CK*28*4)   // 576 * 28 floats = 64512 B

__global__ void __launch_bounds__(256) offset_conv_kernel(
    const float* __restrict__ x,
    const float* __restrict__ wofs,
    const float* __restrict__ bofs)
{
    extern __shared__ float s_w[];   // [c*9+t][28]
    const int tid = threadIdx.x;

    for (int i = tid; i < CK*28; i += 256) {
        int pos = i / 28, oc = i % 28;
        s_w[i] = (oc < OC) ? __ldg(&wofs[oc*CK + pos]) : 0.f;
    }
    __syncthreads();

    const int gid = blockIdx.x * 256 + tid;
    const int ww = gid & (WW-1);
    const int hh = (gid >> 7) & (HH-1);
    const int b  = gid >> 14;

    float acc[28];
#pragma unroll
    for (int oc = 0; oc < 28; oc++) acc[oc] = (oc < OC) ? __ldg(&bofs[oc]) : 0.f;

    const float* xb = x + (size_t)b * CC * HW;

    for (int c = 0; c < CC; c++) {
        const float* xc = xb + c * HW;
#pragma unroll
        for (int t = 0; t < 9; t++) {
            const int dy = t / 3 - 1, dx = t % 3 - 1;
            const int yy = hh + dy, xx = ww + dx;
            float xv = 0.f;
            if (yy >= 0 && yy < HH && xx >= 0 && xx < WW) xv = __ldg(&xc[yy*WW + xx]);
            const float4* wv = (const float4*)(s_w + (c*9 + t) * 28);
#pragma unroll
            for (int q = 0; q < 7; q++) {
                float4 a = wv[q];
                acc[q*4+0] += xv * a.x;
                acc[q*4+1] += xv * a.y;
                acc[q*4+2] += xv * a.z;
                acc[q*4+3] += xv * a.w;
            }
        }
    }

#pragma unroll
    for (int k = 0; k < KT; k++) {
        const float py = acc[k]      + (float)(hh - 1 + k / 3);
        const float px = acc[9 + k]  + (float)(ww - 1 + k % 3);
        const float z  = acc[18 + k];
        const float mv = 1.f / (1.f + __expf(-z));
        const int o = ((b*KT + k) * HH + hh) * WW + ww;
        g_py[o] = py; g_px[o] = px; g_m[o] = mv;
    }
}

// ---------------------------------------------------------------------------
// Kernel 2: fused bilinear gather + GEMM, register-tiled.
// Block = 128 px (one image row) x 64 co. 256 threads, 8 warps.
// Thread computes 8 co x 4 px. K chunked: 8 channels (72 ck rows) per chunk.
// ---------------------------------------------------------------------------
#define PX 128
#define CHUNK_C 8
#define CHUNK_ROWS (CHUNK_C*KT)     // 72
#define WPAD 72

// dynamic smem layout (floats)
#define SO_W4  0                             // 9*128*4  = 4608
#define SO_I4  (SO_W4 + KT*PX*4)             // 4608
#define SO_COL (SO_I4 + KT*PX*4)             // 72*128   = 9216
#define SO_WD  (SO_COL + CHUNK_ROWS*PX)      // 72*72    = 5184
#define K2_FLOATS (SO_WD + CHUNK_ROWS*WPAD)  // 23616
#define K2_SMEM (K2_FLOATS*4)                // 94464 B

__global__ void __launch_bounds__(256, 2) dcn_gemm_kernel(
    const float* __restrict__ x,
    const float* __restrict__ wdcn,
    const float* __restrict__ bdcn,
    float* __restrict__ out)
{
    extern __shared__ float smem[];
    float* s_w4  = smem + SO_W4;
    int*   s_i4  = (int*)(smem + SO_I4);
    float* s_col = smem + SO_COL;
    float* s_wd  = smem + SO_WD;

    const int t    = threadIdx.x;
    const int lane = t & 31;
    const int ty   = t >> 5;            // warp id -> co group (ty*8)

    const int bid = blockIdx.x;
    const int b   = bid >> 7;           // 128 rows per batch
    const int row = bid & 127;

    // ---- prepass: corner weights (mask folded) + clamped flat indices
    for (int idx = t; idx < KT*PX; idx += 256) {
        const int k = idx >> 7, px = idx & 127;
        const int o = ((b*KT + k) * HH + row) * WW + px;
        const float py = g_py[o], pxx = g_px[o], mv = g_m[o];
        const float y0f = floorf(py), x0f = floorf(pxx);
        const float dy = py - y0f, dx = pxx - x0f;
        const int y0 = (int)y0f, x0 = (int)x0f;
        const int y1 = y0 + 1,  x1 = x0 + 1;

        const bool vy0 = (y0 >= 0) & (y0 < HH);
        const bool vy1 = (y1 >= 0) & (y1 < HH);
        const bool vx0 = (x0 >= 0) & (x0 < WW);
        const bool vx1 = (x1 >= 0) & (x1 < WW);
        const int cy0 = min(max(y0, 0), HH-1), cy1 = min(max(y1, 0), HH-1);
        const int cx0 = min(max(x0, 0), WW-1), cx1 = min(max(x1, 0), WW-1);

        float4 wq;
        wq.x = (1.f-dy)*(1.f-dx)*mv * (float)(vy0 & vx0);
        wq.y = (1.f-dy)*dx      *mv * (float)(vy0 & vx1);
        wq.z = dy*(1.f-dx)      *mv * (float)(vy1 & vx0);
        wq.w = dy*dx            *mv * (float)(vy1 & vx1);
        int4 iq;
        iq.x = cy0*WW + cx0;  iq.y = cy0*WW + cx1;
        iq.z = cy1*WW + cx0;  iq.w = cy1*WW + cx1;

        *(float4*)(s_w4 + idx*4) = wq;
        *(int4*)  (s_i4 + idx*4) = iq;
    }
    __syncthreads();

    float acc[32];
#pragma unroll
    for (int j = 0; j < 32; j++) acc[j] = 0.f;

    const float* xb = x + (size_t)b * CC * HW;

    for (int chunk = 0; chunk < CC/CHUNK_C; chunk++) {
        // ---- stage transposed weight chunk: s_wd[kkl*WPAD + co]
        for (int i = t; i < CHUNK_ROWS*CO; i += 256) {
            const int co = i / CHUNK_ROWS;
            const int kkl = i - co*CHUNK_ROWS;
            s_wd[kkl*WPAD + co] = __ldg(&wdcn[co*CK + chunk*CHUNK_ROWS + kkl]);
        }
        // ---- gather chunk: s_col[(cl*9+k)*128 + px]
        for (int idx = t; idx < CHUNK_ROWS*PX; idx += 256) {
            const int r  = idx >> 7, px = idx & 127;
            const int cl = r / 9;
            const int k  = r - cl*9;
            const float* xc = xb + (chunk*CHUNK_C + cl) * HW;
            const int base = (k*PX + px) * 4;
            const float4 wq = *(const float4*)(s_w4 + base);
            const int4   iq = *(const int4*)  (s_i4 + base);
            s_col[idx] = wq.x * __ldg(&xc[iq.x])
                       + wq.y * __ldg(&xc[iq.y])
                       + wq.z * __ldg(&xc[iq.z])
                       + wq.w * __ldg(&xc[iq.w]);
        }
        __syncthreads();

        // ---- GEMM over this chunk's 72 ck rows
#pragma unroll 4
        for (int kkl = 0; kkl < CHUNK_ROWS; kkl++) {
            const float4 cv = *(const float4*)(s_col + kkl*PX + lane*4);
            const float4 w0 = *(const float4*)(s_wd + kkl*WPAD + ty*8);
            const float4 w1 = *(const float4*)(s_wd + kkl*WPAD + ty*8 + 4);
            acc[ 0] += w0.x*cv.x; acc[ 1] += w0.x*cv.y; acc[ 2] += w0.x*cv.z; acc[ 3] += w0.x*cv.w;
            acc[ 4] += w0.y*cv.x; acc[ 5] += w0.y*cv.y; acc[ 6] += w0.y*cv.z; acc[ 7] += w0.y*cv.w;
            acc[ 8] += w0.z*cv.x; acc[ 9] += w0.z*cv.y; acc[10] += w0.z*cv.z; acc[11] += w0.z*cv.w;
            acc[12] += w0.w*cv.x; acc[13] += w0.w*cv.y; acc[14] += w0.w*cv.z; acc[15] += w0.w*cv.w;
            acc[16] += w1.x*cv.x; acc[17] += w1.x*cv.y; acc[18] += w1.x*cv.z; acc[19] += w1.x*cv.w;
            acc[20] += w1.y*cv.x; acc[21] += w1.y*cv.y; acc[22] += w1.y*cv.z; acc[23] += w1.y*cv.w;
            acc[24] += w1.z*cv.x; acc[25] += w1.z*cv.y; acc[26] += w1.z*cv.z; acc[27] += w1.z*cv.w;
            acc[28] += w1.w*cv.x; acc[29] += w1.w*cv.y; acc[30] += w1.w*cv.z; acc[31] += w1.w*cv.w;
        }
        __syncthreads();
    }

    // ---- epilogue: thread owns co = ty*8+j (j=0..7), px = lane*4..lane*4+3
#pragma unroll
    for (int j = 0; j < 8; j++) {
        const int co = ty*8 + j;
        const float bv = __ldg(&bdcn[co]);
        float4 r;
        r.x = acc[j*4+0] + bv;
        r.y = acc[j*4+1] + bv;
        r.z = acc[j*4+2] + bv;
        r.w = acc[j*4+3] + bv;
        *(float4*)&out[((size_t)(b*CO + co)) * HW + row*WW + lane*4] = r;
    }
}

// ---------------------------------------------------------------------------
extern "C" void kernel_launch(void* const* d_in, const int* in_sizes, int n_in,
                              void* d_out, int out_size)
{
    const float* x        = (const float*)d_in[0];
    const float* w_offset = (const float*)d_in[1];
    const float* b_offset = (const float*)d_in[2];
    const float* w_dcn    = (const float*)d_in[3];
    const float* b_dcn    = (const float*)d_in[4];
    float* out = (float*)d_out;

    cudaFuncSetAttribute(offset_conv_kernel,
                         cudaFuncAttributeMaxDynamicSharedMemorySize, K1_SMEM);
    cudaFuncSetAttribute(dcn_gemm_kernel,
                         cudaFuncAttributeMaxDynamicSharedMemorySize, K2_SMEM);

    offset_conv_kernel<<<(BB*HW)/256, 256, K1_SMEM>>>(x, w_offset, b_offset);
    dcn_gemm_kernel<<<BB*HH, 256, K2_SMEM>>>(x, w_dcn, b_dcn, out);
}

// round 6
// speedup vs baseline: 1.7273x; 1.2225x over previous
#include <cuda_runtime.h>
#include <cuda_bf16.h>
#include <cstdint>

#define BB 8
#define CC 64
#define HH 128
#define WW 128
#define HW (HH*WW)
#define KT 9     // taps
#define OC 27    // offset conv output channels
#define CO 64    // dcn output channels
#define CK 576   // C*K

// scratch: sample coords + mask, [B][9][H][W]; split bf16 weights
__device__ float g_py[BB*KT*HW];
__device__ float g_px[BB*KT*HW];
__device__ float g_m [BB*KT*HW];
__device__ __nv_bfloat16 g_wh[CO*CK];
__device__ __nv_bfloat16 g_wl[CO*CK];

// ---------------------------------------------------------------------------
// warp-MMA helpers (plain sm_10x-compatible ISA: ldmatrix + mma.sync bf16)
// ---------------------------------------------------------------------------
__device__ __forceinline__ uint32_t smem_to_u32(const void* p) {
    uint32_t a;
    asm("{ .reg .u64 t; cvta.to.shared.u64 t, %1; cvt.u32.u64 %0, t; }" : "=r"(a) : "l"(p));
    return a;
}
__device__ __forceinline__ void ldsm_x4(uint32_t* r, uint32_t addr) {
    asm volatile("ldmatrix.sync.aligned.m8n8.x4.shared.b16 {%0,%1,%2,%3}, [%4];"
        : "=r"(r[0]), "=r"(r[1]), "=r"(r[2]), "=r"(r[3]) : "r"(addr));
}
__device__ __forceinline__ void mma_bf16(float* d, const uint32_t* a, const uint32_t* b) {
    asm volatile("mma.sync.aligned.m16n8k16.row.col.f32.bf16.bf16.f32 "
        "{%0,%1,%2,%3}, {%4,%5,%6,%7}, {%8,%9}, {%0,%1,%2,%3};"
        : "+f"(d[0]), "+f"(d[1]), "+f"(d[2]), "+f"(d[3])
        : "r"(a[0]), "r"(a[1]), "r"(a[2]), "r"(a[3]), "r"(b[0]), "r"(b[1]));
}

// ---------------------------------------------------------------------------
// Kernel 0: split w_dcn into bf16 hi/lo
// ---------------------------------------------------------------------------
__global__ void wprep_kernel(const float* __restrict__ w) {
    int i = blockIdx.x * 256 + threadIdx.x;
    if (i < CO*CK) {
        float f = w[i];
        __nv_bfloat16 h = __float2bfloat16(f);
        g_wh[i] = h;
        g_wl[i] = __float2bfloat16(f - __bfloat162float(h));
    }
}

// ---------------------------------------------------------------------------
// Kernel 1: offset conv (3x3, pad1, stride1) -> py, px, m (sigmoid applied)
// ---------------------------------------------------------------------------
#define K1_SMEM (CK*28*4)

__global__ void __launch_bounds__(256) offset_conv_kernel(
    const float* __restrict__ x,
    const float* __restrict__ wofs,
    const float* __restrict__ bofs)
{
    extern __shared__ float s_w[];
    const int tid = threadIdx.x;
    for (int i = tid; i < CK*28; i += 256) {
        int pos = i / 28, oc = i % 28;
        s_w[i] = (oc < OC) ? __ldg(&wofs[oc*CK + pos]) : 0.f;
    }
    __syncthreads();

    const int gid = blockIdx.x * 256 + tid;
    const int ww = gid & (WW-1);
    const int hh = (gid >> 7) & (HH-1);
    const int b  = gid >> 14;

    float acc[28];
#pragma unroll
    for (int oc = 0; oc < 28; oc++) acc[oc] = (oc < OC) ? __ldg(&bofs[oc]) : 0.f;

    const float* xb = x + (size_t)b * CC * HW;
    for (int c = 0; c < CC; c++) {
        const float* xc = xb + c * HW;
#pragma unroll
        for (int t = 0; t < 9; t++) {
            const int dy = t / 3 - 1, dx = t % 3 - 1;
            const int yy = hh + dy, xx = ww + dx;
            float xv = 0.f;
            if (yy >= 0 && yy < HH && xx >= 0 && xx < WW) xv = __ldg(&xc[yy*WW + xx]);
            const float4* wv = (const float4*)(s_w + (c*9 + t) * 28);
#pragma unroll
            for (int q = 0; q < 7; q++) {
                float4 a = wv[q];
                acc[q*4+0] += xv * a.x;
                acc[q*4+1] += xv * a.y;
                acc[q*4+2] += xv * a.z;
                acc[q*4+3] += xv * a.w;
            }
        }
    }
#pragma unroll
    for (int k = 0; k < KT; k++) {
        const float py = acc[k]      + (float)(hh - 1 + k / 3);
        const float px = acc[9 + k]  + (float)(ww - 1 + k % 3);
        const float z  = acc[18 + k];
        const float mv = 1.f / (1.f + __expf(-z));
        const int o = ((b*KT + k) * HH + hh) * WW + ww;
        g_py[o] = py; g_px[o] = px; g_m[o] = mv;
    }
}

// ---------------------------------------------------------------------------
// Kernel 2: gather -> bf16x3 mma.sync GEMM.
// Block = one image row: M=128 px, N=64 co, K=576 (9 chunks of 64).
// 8 warps: 4 (px) x 2 (co); warp tile 32x32, bf16x3 via mma.m16n8k16.
// ---------------------------------------------------------------------------
#define SA_STRIDE 72                       // bf16, padded (mult of 8)
// smem layout (bytes)
#define SO_W4   0                          // 9*128 float4 = 18432
#define SO_IDX  18432                      // 9*128 u32    = 4608
#define SO_A    23040                      // A hi: 128*72*2 = 18432
#define SO_AL   (SO_A  + 18432)            // A lo
#define SO_B    (SO_AL + 18432)            // B hi: 64*72*2 = 9216
#define SO_BL   (SO_B  + 9216)
#define K2_SMEM (SO_BL + 9216)             // 78336 B -> 2 blocks/SM
// epilogue staging aliases the A region (per-warp 32x33 floats)
#define EP_FLOATS (32*33)

__global__ void __launch_bounds__(256, 2) dcn_mma_kernel(
    const float* __restrict__ x,
    const float* __restrict__ bdcn,
    float* __restrict__ out)
{
    extern __shared__ char smem[];
    float*    s_w4  = (float*)(smem + SO_W4);
    uint32_t* s_idx = (uint32_t*)(smem + SO_IDX);

    const int tid  = threadIdx.x;
    const int wid  = tid >> 5;
    const int lane = tid & 31;
    const int b    = blockIdx.x >> 7;
    const int row  = blockIdx.x & 127;

    // ---- prepass: corner weights (mask+validity folded) + packed indices
    for (int i = tid; i < KT*128; i += 256) {
        const int k = i >> 7, px = i & 127;
        const int o = ((b*KT + k)*HH + row)*WW + px;
        const float py = g_py[o], pxx = g_px[o], mv = g_m[o];
        const float y0f = floorf(py), x0f = floorf(pxx);
        const float dy = py - y0f, dx = pxx - x0f;
        const int y0 = (int)y0f, x0 = (int)x0f, y1 = y0+1, x1 = x0+1;
        const bool vy0 = (y0>=0)&(y0<HH), vy1 = (y1>=0)&(y1<HH);
        const bool vx0 = (x0>=0)&(x0<WW), vx1 = (x1>=0)&(x1<WW);
        const int cy0 = min(max(y0,0),HH-1), cy1 = min(max(y1,0),HH-1);
        const int cx0 = min(max(x0,0),WW-1), cx1 = min(max(x1,0),WW-1);
        float4 wq;
        wq.x = (1.f-dy)*(1.f-dx)*mv * (float)(vy0&vx0);
        wq.y = (1.f-dy)*dx      *mv * (float)(vy0&vx1);
        wq.z = dy*(1.f-dx)      *mv * (float)(vy1&vx0);
        wq.w = dy*dx            *mv * (float)(vy1&vx1);
        *(float4*)(s_w4 + i*4) = wq;
        s_idx[i] = (uint32_t)cy0 | ((uint32_t)cx0<<8) | ((uint32_t)cy1<<16) | ((uint32_t)cx1<<24);
    }
    __syncthreads();

    // ---- warp tiling + ldmatrix lane addresses
    const int wm  = wid >> 1;            // 0..3 -> px tile
    const int wn  = wid & 1;             // 0..1 -> co tile
    const int px0 = wm * 32;
    const int co0 = wn * 32;

    const uint32_t sb_ah = smem_to_u32(smem + SO_A);
    const uint32_t sb_al = smem_to_u32(smem + SO_AL);
    const uint32_t sb_bh = smem_to_u32(smem + SO_B);
    const uint32_t sb_bl = smem_to_u32(smem + SO_BL);

    // A: row = px0 + (lane&15), col-half = ((lane>>4)&1)*8
    const uint32_t a_lane = (uint32_t)(((px0 + (lane & 15)) * SA_STRIDE
                                       + ((lane >> 4) & 1) * 8) * 2);
    // B: row = co0 + ((lane>>4)&1)*8 + (lane&7), col-half = ((lane>>3)&1)*8
    const uint32_t b_lane = (uint32_t)(((co0 + ((lane >> 4) & 1) * 8 + (lane & 7)) * SA_STRIDE
                                       + ((lane >> 3) & 1) * 8) * 2);

    float acc[2][4][4];
#pragma unroll
    for (int m = 0; m < 2; m++)
#pragma unroll
        for (int n = 0; n < 4; n++)
#pragma unroll
            for (int q = 0; q < 4; q++) acc[m][n][q] = 0.f;

    const float* xb = x + (size_t)b * CC * HW;
    __nv_bfloat16* s_ah = (__nv_bfloat16*)(smem + SO_A);
    __nv_bfloat16* s_al = (__nv_bfloat16*)(smem + SO_AL);
    __nv_bfloat16* s_bh = (__nv_bfloat16*)(smem + SO_B);
    __nv_bfloat16* s_bl = (__nv_bfloat16*)(smem + SO_BL);

    for (int c = 0; c < 9; c++) {
        // ---- gather chunk c into A (hi/lo), row-major [px][k], stride 72
#pragma unroll 4
        for (int idx = tid; idx < 64*128; idx += 256) {
            const int kr = idx >> 7;          // 0..63
            const int px = idx & 127;
            const int kg = c*64 + kr;
            const int ch = kg / 9;
            const int tp = kg - ch*9;
            const float* xc = xb + ch * HW;
            const int e = tp*128 + px;
            const float4 wq = *(const float4*)(s_w4 + e*4);
            const uint32_t pi = s_idx[e];
            const int cy0 = pi & 255, cx0 = (pi>>8)&255, cy1 = (pi>>16)&255, cx1 = pi>>24;
            const float v = wq.x*__ldg(&xc[cy0*WW+cx0]) + wq.y*__ldg(&xc[cy0*WW+cx1])
                          + wq.z*__ldg(&xc[cy1*WW+cx0]) + wq.w*__ldg(&xc[cy1*WW+cx1]);
            const __nv_bfloat16 vh = __float2bfloat16(v);
            const __nv_bfloat16 vl = __float2bfloat16(v - __bfloat162float(vh));
            s_ah[px*SA_STRIDE + kr] = vh;
            s_al[px*SA_STRIDE + kr] = vl;
        }
        // ---- stage B chunk (weights hi/lo), row-major [co][k]
#pragma unroll
        for (int idx = tid; idx < 64*64; idx += 256) {
            const int co = idx >> 6, kr = idx & 63;
            const int gi = co*CK + c*64 + kr;
            s_bh[co*SA_STRIDE + kr] = __ldg(&g_wh[gi]);
            s_bl[co*SA_STRIDE + kr] = __ldg(&g_wl[gi]);
        }
        __syncthreads();

        // ---- warp MMAs: 4 k-steps of 16
#pragma unroll
        for (int ks = 0; ks < 4; ks++) {
            const uint32_t kofs = ks * 32;                 // 16 bf16 = 32 B
            uint32_t ah[2][4], al[2][4], bh[2][4], bl[2][4];
            ldsm_x4(ah[0], sb_ah + a_lane + kofs);
            ldsm_x4(ah[1], sb_ah + a_lane + 16*SA_STRIDE*2 + kofs);
            ldsm_x4(al[0], sb_al + a_lane + kofs);
            ldsm_x4(al[1], sb_al + a_lane + 16*SA_STRIDE*2 + kofs);
            ldsm_x4(bh[0], sb_bh + b_lane + kofs);
            ldsm_x4(bh[1], sb_bh + b_lane + 16*SA_STRIDE*2 + kofs);
            ldsm_x4(bl[0], sb_bl + b_lane + kofs);
            ldsm_x4(bl[1], sb_bl + b_lane + 16*SA_STRIDE*2 + kofs);
#pragma unroll
            for (int m = 0; m < 2; m++) {
#pragma unroll
                for (int n = 0; n < 4; n++) {
                    const uint32_t* bhp = &bh[n>>1][(n&1)*2];
                    const uint32_t* blp = &bl[n>>1][(n&1)*2];
                    mma_bf16(acc[m][n], ah[m], bhp);
                    mma_bf16(acc[m][n], ah[m], blp);
                    mma_bf16(acc[m][n], al[m], bhp);
                }
            }
        }
        __syncthreads();
    }

    // ---- epilogue: per-warp transpose through smem (aliases A region)
    float* s_ep = (float*)(smem + SO_A) + wid * EP_FLOATS;
#pragma unroll
    for (int m = 0; m < 2; m++) {
#pragma unroll
        for (int n = 0; n < 4; n++) {
            const int pxl = m*16 + (lane >> 2);
            const int col = n*8 + (lane & 3)*2;
            s_ep[ col     *33 + pxl    ] = acc[m][n][0];
            s_ep[(col + 1)*33 + pxl    ] = acc[m][n][1];
            s_ep[ col     *33 + pxl + 8] = acc[m][n][2];
            s_ep[(col + 1)*33 + pxl + 8] = acc[m][n][3];
        }
    }
    __syncwarp();

    float* ob = out + (size_t)b*CO*HW + row*WW + px0;
#pragma unroll
    for (int col = 0; col < 32; col++) {
        const int co = co0 + col;
        ob[(size_t)co*HW + lane] = s_ep[col*33 + lane] + __ldg(&bdcn[co]);
    }
}

// ---------------------------------------------------------------------------
extern "C" void kernel_launch(void* const* d_in, const int* in_sizes, int n_in,
                              void* d_out, int out_size)
{
    const float* x        = (const float*)d_in[0];
    const float* w_offset = (const float*)d_in[1];
    const float* b_offset = (const float*)d_in[2];
    const float* w_dcn    = (const float*)d_in[3];
    const float* b_dcn    = (const float*)d_in[4];
    float* out = (float*)d_out;

    cudaFuncSetAttribute(offset_conv_kernel,
                         cudaFuncAttributeMaxDynamicSharedMemorySize, K1_SMEM);
    cudaFuncSetAttribute(dcn_mma_kernel,
                         cudaFuncAttributeMaxDynamicSharedMemorySize, K2_SMEM);

    wprep_kernel<<<(CO*CK + 255)/256, 256>>>(w_dcn);
    offset_conv_kernel<<<(BB*HW)/256, 256, K1_SMEM>>>(x, w_offset, b_offset);
    dcn_mma_kernel<<<BB*HH, 256, K2_SMEM>>>(x, b_dcn, out);
}

// round 7
// speedup vs baseline: 1.7786x; 1.0297x over previous
#include <cuda_runtime.h>
#include <cuda_bf16.h>
#include <cstdint>

#define BB 8
#define CC 64
#define HH 128
#define WW 128
#define HW (HH*WW)
#define KT 9     // taps
#define OC 27    // offset conv output channels
#define CO 64    // dcn output channels
#define CK 576   // C*K

// split bf16 weights (dcn + offset conv)
__device__ __nv_bfloat16 g_wh[CO*CK];
__device__ __nv_bfloat16 g_wl[CO*CK];
__device__ __nv_bfloat16 g_oh[OC*CK];
__device__ __nv_bfloat16 g_ol[OC*CK];
// per-(b,tap,pixel) corner weights + packed clamped indices
__device__ float4   g_w4 [BB*KT*HW];
__device__ uint32_t g_idx[BB*KT*HW];

// ---------------------------------------------------------------------------
// warp-MMA helpers (plain sm_10x-compatible ISA: ldmatrix + mma.sync bf16)
// ---------------------------------------------------------------------------
__device__ __forceinline__ uint32_t smem_to_u32(const void* p) {
    uint32_t a;
    asm("{ .reg .u64 t; cvta.to.shared.u64 t, %1; cvt.u32.u64 %0, t; }" : "=r"(a) : "l"(p));
    return a;
}
__device__ __forceinline__ void ldsm_x4(uint32_t* r, uint32_t addr) {
    asm volatile("ldmatrix.sync.aligned.m8n8.x4.shared.b16 {%0,%1,%2,%3}, [%4];"
        : "=r"(r[0]), "=r"(r[1]), "=r"(r[2]), "=r"(r[3]) : "r"(addr));
}
__device__ __forceinline__ void ldsm_x4_t(uint32_t* r, uint32_t addr) {
    asm volatile("ldmatrix.sync.aligned.m8n8.x4.trans.shared.b16 {%0,%1,%2,%3}, [%4];"
        : "=r"(r[0]), "=r"(r[1]), "=r"(r[2]), "=r"(r[3]) : "r"(addr));
}
__device__ __forceinline__ void mma_bf16(float* d, const uint32_t* a, const uint32_t* b) {
    asm volatile("mma.sync.aligned.m16n8k16.row.col.f32.bf16.bf16.f32 "
        "{%0,%1,%2,%3}, {%4,%5,%6,%7}, {%8,%9}, {%0,%1,%2,%3};"
        : "+f"(d[0]), "+f"(d[1]), "+f"(d[2]), "+f"(d[3])
        : "r"(a[0]), "r"(a[1]), "r"(a[2]), "r"(a[3]), "r"(b[0]), "r"(b[1]));
}
__device__ __forceinline__ void bf16split(float v, __nv_bfloat16& h, __nv_bfloat16& l) {
    h = __float2bfloat16(v);
    l = __float2bfloat16(v - __bfloat162float(h));
}

// A tiles stored [k][px], stride 136 bf16 (272 B: odd # of 16B units)
#define KSTR 136

// ---------------------------------------------------------------------------
// Kernel 0: split w_dcn + w_offset into bf16 hi/lo
// ---------------------------------------------------------------------------
#define WPN (CO*CK + OC*CK)   // 36864 + 15552
__global__ void wprep_kernel(const float* __restrict__ wd, const float* __restrict__ wo) {
    int i = blockIdx.x * 256 + threadIdx.x;
    if (i >= WPN) return;
    if (i < CO*CK) bf16split(wd[i], g_wh[i], g_wl[i]);
    else { int j = i - CO*CK; bf16split(wo[j], g_oh[j], g_ol[j]); }
}

// ---------------------------------------------------------------------------
// Kernel 1: offset conv as bf16x3 implicit GEMM (M=128 px, N=32, K=576),
// epilogue computes corner weights + packed indices directly.
// ---------------------------------------------------------------------------
#define S1_A   0
#define S1_AL  (S1_A  + 64*KSTR*2)   // 17408
#define S1_B   (S1_AL + 64*KSTR*2)   // 34816
#define S1_BL  (S1_B  + 32*72*2)     // +4608
#define K1_SMEM (S1_BL + 32*72*2)    // 44032
// epilogue float staging aliases A region: 128*33*4 = 16896 <= 17408

__global__ void __launch_bounds__(256, 2) offset_mma_kernel(
    const float* __restrict__ x,
    const float* __restrict__ bofs)
{
    extern __shared__ char smem[];
    __nv_bfloat16* s_ah = (__nv_bfloat16*)(smem + S1_A);
    __nv_bfloat16* s_al = (__nv_bfloat16*)(smem + S1_AL);
    __nv_bfloat16* s_bh = (__nv_bfloat16*)(smem + S1_B);
    __nv_bfloat16* s_bl = (__nv_bfloat16*)(smem + S1_BL);

    const int tid  = threadIdx.x;
    const int wid  = tid >> 5;
    const int lane = tid & 31;
    const int b    = blockIdx.x >> 7;
    const int row  = blockIdx.x & 127;

    const int px  = tid & 127;       // fixed px per thread for A build
    const int kr0 = tid >> 7;

    // ldsm addresses
    const uint32_t sb_ah = smem_to_u32(s_ah);
    const uint32_t sb_al = smem_to_u32(s_al);
    const uint32_t sb_bh = smem_to_u32(s_bh);
    const uint32_t sb_bl = smem_to_u32(s_bl);
    // A (trans, [k][px]): matrix j=lane>>3: m_off=(j&1)*8, k_off=(j>>1)*8, r=lane&7
    const int aj = lane >> 3;
    const uint32_t a_lane = (uint32_t)((((aj >> 1) * 8 + (lane & 7)) * KSTR
                                        + wid * 16 + (aj & 1) * 8) * 2);
    // B (non-trans, [oc][k] stride 72)
    const uint32_t b_lane = (uint32_t)(((((lane >> 4) & 1) * 8 + (lane & 7)) * 72
                                        + ((lane >> 3) & 1) * 8) * 2);

    float acc[4][4];
#pragma unroll
    for (int n = 0; n < 4; n++)
#pragma unroll
        for (int q = 0; q < 4; q++) acc[n][q] = 0.f;

    const float* xb = x + (size_t)b * CC * HW;

    for (int c = 0; c < 9; c++) {
        // ---- A build: im2col chunk, [k][px], 1 LDG per element
#pragma unroll 4
        for (int i2 = 0; i2 < 32; i2++) {
            const int kr = kr0 + i2*2;
            const int kg = c*64 + kr;
            const int ch = kg / 9;
            const int tp = kg - ch*9;
            const int dy = tp/3 - 1, dx = tp - (tp/3)*3 - 1;
            const int yy = row + dy, xx = px + dx;
            float v = 0.f;
            if ((unsigned)yy < HH && (unsigned)xx < WW)
                v = __ldg(&xb[ch*HW + yy*WW + xx]);
            __nv_bfloat16 vh, vl; bf16split(v, vh, vl);
            s_ah[kr*KSTR + px] = vh;
            s_al[kr*KSTR + px] = vl;
        }
        // ---- B build: [oc][k], oc>=27 zero
#pragma unroll
        for (int i2 = 0; i2 < 8; i2++) {
            const int idx = tid + i2*256;
            const int oc = idx >> 6, kr = idx & 63;
            __nv_bfloat16 vh = __float2bfloat16(0.f), vl = vh;
            if (oc < OC) {
                const int gi = oc*CK + c*64 + kr;
                vh = g_oh[gi]; vl = g_ol[gi];
            }
            s_bh[oc*72 + kr] = vh;
            s_bl[oc*72 + kr] = vl;
        }
        __syncthreads();

        // ---- MMA: 4 ksteps of 16
#pragma unroll
        for (int ks = 0; ks < 4; ks++) {
            const uint32_t ao = (uint32_t)(ks * 16 * KSTR * 2);
            const uint32_t bo = (uint32_t)(ks * 32);
            uint32_t ah[4], al[4], bh[2][4], bl[2][4];
            ldsm_x4_t(ah, sb_ah + a_lane + ao);
            ldsm_x4_t(al, sb_al + a_lane + ao);
            ldsm_x4(bh[0], sb_bh + b_lane + bo);
            ldsm_x4(bh[1], sb_bh + b_lane + 16*72*2 + bo);
            ldsm_x4(bl[0], sb_bl + b_lane + bo);
            ldsm_x4(bl[1], sb_bl + b_lane + 16*72*2 + bo);
#pragma unroll
            for (int n = 0; n < 4; n++) {
                const uint32_t* bhp = &bh[n>>1][(n&1)*2];
                const uint32_t* blp = &bl[n>>1][(n&1)*2];
                mma_bf16(acc[n], ah, bhp);
                mma_bf16(acc[n], ah, blp);
                mma_bf16(acc[n], al, bhp);
            }
        }
        __syncthreads();
    }

    // ---- stage results [px][oc] (stride 33) in smem (aliases A)
    float* s_out = (float*)(smem + S1_A);
#pragma unroll
    for (int n = 0; n < 4; n++) {
#pragma unroll
        for (int q = 0; q < 4; q++) {
            const int pr = wid*16 + (lane >> 2) + 8*(q >> 1);
            const int oc = n*8 + (lane & 3)*2 + (q & 1);
            s_out[pr*33 + oc] = acc[n][q];
        }
    }
    __syncthreads();

    // ---- epilogue: corner weights + packed indices per (k, px)
    for (int i = tid; i < KT*128; i += 256) {
        const int k = i >> 7, p = i & 127;
        const float oy = s_out[p*33 + k]      + __ldg(&bofs[k]);
        const float ox = s_out[p*33 + 9 + k]  + __ldg(&bofs[9 + k]);
        const float z  = s_out[p*33 + 18 + k] + __ldg(&bofs[18 + k]);
        const float mv = 1.f / (1.f + __expf(-z));
        const float py  = oy + (float)(row - 1 + k/3);
        const float pxx = ox + (float)(p   - 1 + k%3);
        const float y0f = floorf(py), x0f = floorf(pxx);
        const float dy = py - y0f, dx = pxx - x0f;
        const int y0 = (int)y0f, x0 = (int)x0f, y1 = y0+1, x1 = x0+1;
        const bool vy0 = (y0>=0)&(y0<HH), vy1 = (y1>=0)&(y1<HH);
        const bool vx0 = (x0>=0)&(x0<WW), vx1 = (x1>=0)&(x1<WW);
        const int cy0 = min(max(y0,0),HH-1), cy1 = min(max(y1,0),HH-1);
        const int cx0 = min(max(x0,0),WW-1), cx1 = min(max(x1,0),WW-1);
        float4 wq;
        wq.x = (1.f-dy)*(1.f-dx)*mv * (float)(vy0&vx0);
        wq.y = (1.f-dy)*dx      *mv * (float)(vy0&vx1);
        wq.z = dy*(1.f-dx)      *mv * (float)(vy1&vx0);
        wq.w = dy*dx            *mv * (float)(vy1&vx1);
        const int o = ((b*KT + k)*HH + row)*WW + p;
        g_w4[o]  = wq;
        g_idx[o] = (uint32_t)cy0 | ((uint32_t)cx0<<8) | ((uint32_t)cy1<<16) | ((uint32_t)cx1<<24);
    }
}

// ---------------------------------------------------------------------------
// Kernel 2: gather -> bf16x3 mma.sync GEMM.
// Block = one image row: M=128 px, N=64 co, K=576 (9 chunks of 64).
// 8 warps: 4 (px) x 2 (co); warp tile 32x32. A stored [k][px] stride 136.
// ---------------------------------------------------------------------------
#define SO_W4   0                          // 9*128 float4 = 18432
#define SO_IDX  18432                      // 9*128 u32    = 4608
#define SO_A    23040                      // A hi: 64*136*2 = 17408
#define SO_AL   (SO_A  + 64*KSTR*2)        // 40448
#define SO_B    (SO_AL + 64*KSTR*2)        // 57856: B hi 64*72*2 = 9216
#define SO_BL   (SO_B  + 9216)
#define K2_SMEM (SO_BL + 9216)             // 76288 -> 2 blocks/SM
#define EP_FLOATS (32*33)                  // epilogue per-warp, aliases A

__global__ void __launch_bounds__(256, 2) dcn_mma_kernel(
    const float* __restrict__ x,
    const float* __restrict__ bdcn,
    float* __restrict__ out)
{
    extern __shared__ char smem[];
    float*    s_w4  = (float*)(smem + SO_W4);
    uint32_t* s_idx = (uint32_t*)(smem + SO_IDX);

    const int tid  = threadIdx.x;
    const int wid  = tid >> 5;
    const int lane = tid & 31;
    const int b    = blockIdx.x >> 7;
    const int row  = blockIdx.x & 127;

    // ---- prepass: copy precomputed corner weights + indices
    {
        const int gbase = (b*KT*HH + row)*WW;   // + k*HH*WW + px
        for (int i = tid; i < KT*128; i += 256) {
            const int k = i >> 7, p = i & 127;
            const int o = gbase + k*HW + p;
            *(float4*)(s_w4 + i*4) = g_w4[o];
            s_idx[i] = g_idx[o];
        }
    }
    __syncthreads();

    // ---- warp tiling + ldsm lane addresses
    const int wm  = wid >> 1;            // 0..3 -> px tile
    const int wn  = wid & 1;             // 0..1 -> co tile
    const int px0 = wm * 32;
    const int co0 = wn * 32;

    const uint32_t sb_ah = smem_to_u32(smem + SO_A);
    const uint32_t sb_al = smem_to_u32(smem + SO_AL);
    const uint32_t sb_bh = smem_to_u32(smem + SO_B);
    const uint32_t sb_bl = smem_to_u32(smem + SO_BL);

    // A (trans, [k][px]): matrix j=lane>>3: m_off=(j&1)*8, k_off=(j>>1)*8
    const int aj = lane >> 3;
    const uint32_t a_lane = (uint32_t)((((aj >> 1) * 8 + (lane & 7)) * KSTR
                                        + px0 + (aj & 1) * 8) * 2);
    // B (non-trans, [co][k] stride 72)
    const uint32_t b_lane = (uint32_t)(((co0 + ((lane >> 4) & 1) * 8 + (lane & 7)) * 72
                                        + ((lane >> 3) & 1) * 8) * 2);

    float acc[2][4][4];
#pragma unroll
    for (int m = 0; m < 2; m++)
#pragma unroll
        for (int n = 0; n < 4; n++)
#pragma unroll
            for (int q = 0; q < 4; q++) acc[m][n][q] = 0.f;

    const float* xb = x + (size_t)b * CC * HW;
    __nv_bfloat16* s_ah = (__nv_bfloat16*)(smem + SO_A);
    __nv_bfloat16* s_al = (__nv_bfloat16*)(smem + SO_AL);
    __nv_bfloat16* s_bh = (__nv_bfloat16*)(smem + SO_B);
    __nv_bfloat16* s_bl = (__nv_bfloat16*)(smem + SO_BL);

    const int gpx = tid & 127;           // fixed px per thread for gather
    const int gk0 = tid >> 7;

    for (int c = 0; c < 9; c++) {
        // ---- gather chunk c into A (hi/lo), [k][px]
#pragma unroll 4
        for (int i2 = 0; i2 < 32; i2++) {
            const int kr = gk0 + i2*2;
            const int kg = c*64 + kr;
            const int ch = kg / 9;
            const int tp = kg - ch*9;
            const float* xc = xb + ch * HW;
            const int e = tp*128 + gpx;
            const float4 wq = *(const float4*)(s_w4 + e*4);
            const uint32_t pi = s_idx[e];
            const int cy0 = pi & 255, cx0 = (pi>>8)&255, cy1 = (pi>>16)&255, cx1 = pi>>24;
            const float v = wq.x*__ldg(&xc[cy0*WW+cx0]) + wq.y*__ldg(&xc[cy0*WW+cx1])
                          + wq.z*__ldg(&xc[cy1*WW+cx0]) + wq.w*__ldg(&xc[cy1*WW+cx1]);
            __nv_bfloat16 vh, vl; bf16split(v, vh, vl);
            s_ah[kr*KSTR + gpx] = vh;
            s_al[kr*KSTR + gpx] = vl;
        }
        // ---- stage B chunk (weights hi/lo), [co][k]
#pragma unroll
        for (int i2 = 0; i2 < 16; i2++) {
            const int idx = tid + i2*256;
            const int co = idx >> 6, kr = idx & 63;
            const int gi = co*CK + c*64 + kr;
            s_bh[co*72 + kr] = g_wh[gi];
            s_bl[co*72 + kr] = g_wl[gi];
        }
        __syncthreads();

        // ---- warp MMAs: 4 k-steps of 16
#pragma unroll
        for (int ks = 0; ks < 4; ks++) {
            const uint32_t ao = (uint32_t)(ks * 16 * KSTR * 2);
            const uint32_t bo = (uint32_t)(ks * 32);
            uint32_t ah[2][4], al[2][4], bh[2][4], bl[2][4];
            ldsm_x4_t(ah[0], sb_ah + a_lane + ao);
            ldsm_x4_t(ah[1], sb_ah + a_lane + ao + 32);       // +16 px
            ldsm_x4_t(al[0], sb_al + a_lane + ao);
            ldsm_x4_t(al[1], sb_al + a_lane + ao + 32);
            ldsm_x4(bh[0], sb_bh + b_lane + bo);
            ldsm_x4(bh[1], sb_bh + b_lane + 16*72*2 + bo);
            ldsm_x4(bl[0], sb_bl + b_lane + bo);
            ldsm_x4(bl[1], sb_bl + b_lane + 16*72*2 + bo);
#pragma unroll
            for (int m = 0; m < 2; m++) {
#pragma unroll
                for (int n = 0; n < 4; n++) {
                    const uint32_t* bhp = &bh[n>>1][(n&1)*2];
                    const uint32_t* blp = &bl[n>>1][(n&1)*2];
                    mma_bf16(acc[m][n], ah[m], bhp);
                    mma_bf16(acc[m][n], ah[m], blp);
                    mma_bf16(acc[m][n], al[m], bhp);
                }
            }
        }
        __syncthreads();
    }

    // ---- epilogue: per-warp transpose through smem (aliases A region)
    float* s_ep = (float*)(smem + SO_A) + wid * EP_FLOATS;
#pragma unroll
    for (int m = 0; m < 2; m++) {
#pragma unroll
        for (int n = 0; n < 4; n++) {
            const int pxl = m*16 + (lane >> 2);
            const int col = n*8 + (lane & 3)*2;
            s_ep[ col     *33 + pxl    ] = acc[m][n][0];
            s_ep[(col + 1)*33 + pxl    ] = acc[m][n][1];
            s_ep[ col     *33 + pxl + 8] = acc[m][n][2];
            s_ep[(col + 1)*33 + pxl + 8] = acc[m][n][3];
        }
    }
    __syncwarp();

    float* ob = out + (size_t)b*CO*HW + row*WW + px0;
#pragma unroll
    for (int col = 0; col < 32; col++) {
        const int co = co0 + col;
        ob[(size_t)co*HW + lane] = s_ep[col*33 + lane] + __ldg(&bdcn[co]);
    }
}

// ---------------------------------------------------------------------------
extern "C" void kernel_launch(void* const* d_in, const int* in_sizes, int n_in,
                              void* d_out, int out_size)
{
    const float* x        = (const float*)d_in[0];
    const float* w_offset = (const float*)d_in[1];
    const float* b_offset = (const float*)d_in[2];
    const float* w_dcn    = (const float*)d_in[3];
    const float* b_dcn    = (const float*)d_in[4];
    float* out = (float*)d_out;

    cudaFuncSetAttribute(offset_mma_kernel,
                         cudaFuncAttributeMaxDynamicSharedMemorySize, K1_SMEM);
    cudaFuncSetAttribute(dcn_mma_kernel,
                         cudaFuncAttributeMaxDynamicSharedMemorySize, K2_SMEM);

    wprep_kernel<<<(WPN + 255)/256, 256>>>(w_dcn, w_offset);
    offset_mma_kernel<<<BB*HH, 256, K1_SMEM>>>(x, b_offset);
    dcn_mma_kernel<<<BB*HH, 256, K2_SMEM>>>(x, b_dcn, out);
}

// round 10
// speedup vs baseline: 2.4511x; 1.3781x over previous
#include <cuda_runtime.h>
#include <cuda_bf16.h>
#include <cstdint>

#define BB 8
#define CC 64
#define HH 128
#define WW 128
#define HW (HH*WW)
#define KT 9     // taps
#define OC 27    // offset conv output channels
#define CO 64    // dcn output channels
#define CK 576   // C*K

// split bf16 weights (dcn + offset conv)
__device__ __nv_bfloat16 g_wh[CO*CK];
__device__ __nv_bfloat16 g_wl[CO*CK];
__device__ __nv_bfloat16 g_oh[OC*CK];
__device__ __nv_bfloat16 g_ol[OC*CK];
// per-(b,tap,pixel) corner weights + packed clamped indices
__device__ float4   g_w4 [BB*KT*HW];
__device__ uint32_t g_idx[BB*KT*HW];

// ---------------------------------------------------------------------------
// warp-MMA helpers (plain sm_10x-compatible ISA: ldmatrix + mma.sync bf16)
// ---------------------------------------------------------------------------
__device__ __forceinline__ uint32_t smem_to_u32(const void* p) {
    uint32_t a;
    asm("{ .reg .u64 t; cvta.to.shared.u64 t, %1; cvt.u32.u64 %0, t; }" : "=r"(a) : "l"(p));
    return a;
}
__device__ __forceinline__ void ldsm_x4(uint32_t* r, uint32_t addr) {
    asm volatile("ldmatrix.sync.aligned.m8n8.x4.shared.b16 {%0,%1,%2,%3}, [%4];"
        : "=r"(r[0]), "=r"(r[1]), "=r"(r[2]), "=r"(r[3]) : "r"(addr));
}
__device__ __forceinline__ void ldsm_x4_t(uint32_t* r, uint32_t addr) {
    asm volatile("ldmatrix.sync.aligned.m8n8.x4.trans.shared.b16 {%0,%1,%2,%3}, [%4];"
        : "=r"(r[0]), "=r"(r[1]), "=r"(r[2]), "=r"(r[3]) : "r"(addr));
}
__device__ __forceinline__ void mma_bf16(float* d, const uint32_t* a, const uint32_t* b) {
    asm volatile("mma.sync.aligned.m16n8k16.row.col.f32.bf16.bf16.f32 "
        "{%0,%1,%2,%3}, {%4,%5,%6,%7}, {%8,%9}, {%0,%1,%2,%3};"
        : "+f"(d[0]), "+f"(d[1]), "+f"(d[2]), "+f"(d[3])
        : "r"(a[0]), "r"(a[1]), "r"(a[2]), "r"(a[3]), "r"(b[0]), "r"(b[1]));
}
__device__ __forceinline__ void bf16split(float v, __nv_bfloat16& h, __nv_bfloat16& l) {
    h = __float2bfloat16(v);
    l = __float2bfloat16(v - __bfloat162float(h));
}

// A tiles stored [k][px], stride 136 bf16 (272 B: odd # of 16B units)
#define KSTR 136

// ---------------------------------------------------------------------------
// Kernel 0: split w_dcn + w_offset into bf16 hi/lo
// ---------------------------------------------------------------------------
#define WPN (CO*CK + OC*CK)
__global__ void wprep_kernel(const float* __restrict__ wd, const float* __restrict__ wo) {
    int i = blockIdx.x * 256 + threadIdx.x;
    if (i >= WPN) return;
    if (i < CO*CK) bf16split(wd[i], g_wh[i], g_wl[i]);
    else { int j = i - CO*CK; bf16split(wo[j], g_oh[j], g_ol[j]); }
}

// ---------------------------------------------------------------------------
// Kernel 1: offset conv as bf16x3 implicit GEMM (M=128 px, N=32, K=576),
// software-pipelined: im2col chunk c+1 prefetched to regs during MMA(c).
// ---------------------------------------------------------------------------
#define S1_A   0
#define S1_AL  (S1_A  + 64*KSTR*2)   // 17408
#define S1_B   (S1_AL + 64*KSTR*2)   // 34816
#define S1_BL  (S1_B  + 32*72*2)     // +4608
#define K1_SMEM (S1_BL + 32*72*2)    // 44032

__device__ __forceinline__ void im2col_fetch(
    const float* __restrict__ xb, int row, int px, int kr0, int c, float* v)
{
#pragma unroll
    for (int i2 = 0; i2 < 32; i2++) {
        const int kr = kr0 + i2*2;
        const int kg = c*64 + kr;
        const int ch = kg / 9;
        const int tp = kg - ch*9;
        const int dy = tp/3 - 1, dx = tp - (tp/3)*3 - 1;
        const int yy = row + dy, xx = px + dx;
        float val = 0.f;
        if ((unsigned)yy < HH && (unsigned)xx < WW)
            val = __ldg(&xb[ch*HW + yy*WW + xx]);
        v[i2] = val;
    }
}

__global__ void __launch_bounds__(256, 2) offset_mma_kernel(
    const float* __restrict__ x,
    const float* __restrict__ bofs)
{
    extern __shared__ char smem[];
    __nv_bfloat16* s_ah = (__nv_bfloat16*)(smem + S1_A);
    __nv_bfloat16* s_al = (__nv_bfloat16*)(smem + S1_AL);
    __nv_bfloat16* s_bh = (__nv_bfloat16*)(smem + S1_B);
    __nv_bfloat16* s_bl = (__nv_bfloat16*)(smem + S1_BL);

    const int tid  = threadIdx.x;
    const int wid  = tid >> 5;
    const int lane = tid & 31;
    const int b    = blockIdx.x >> 7;
    const int row  = blockIdx.x & 127;

    const int px  = tid & 127;
    const int kr0 = tid >> 7;

    const uint32_t sb_ah = smem_to_u32(s_ah);
    const uint32_t sb_al = smem_to_u32(s_al);
    const uint32_t sb_bh = smem_to_u32(s_bh);
    const uint32_t sb_bl = smem_to_u32(s_bl);
    const int aj = lane >> 3;
    const uint32_t a_lane = (uint32_t)((((aj >> 1) * 8 + (lane & 7)) * KSTR
                                        + wid * 16 + (aj & 1) * 8) * 2);
    const uint32_t b_lane = (uint32_t)(((((lane >> 4) & 1) * 8 + (lane & 7)) * 72
                                        + ((lane >> 3) & 1) * 8) * 2);

    float acc[4][4];
#pragma unroll
    for (int n = 0; n < 4; n++)
#pragma unroll
        for (int q = 0; q < 4; q++) acc[n][q] = 0.f;

    const float* xb = x + (size_t)b * CC * HW;

    float v[32];
    im2col_fetch(xb, row, px, kr0, 0, v);

    for (int c = 0; c < 9; c++) {
        // ---- store prefetched A chunk (hi/lo)
#pragma unroll
        for (int i2 = 0; i2 < 32; i2++) {
            const int kr = kr0 + i2*2;
            __nv_bfloat16 vh, vl; bf16split(v[i2], vh, vl);
            s_ah[kr*KSTR + px] = vh;
            s_al[kr*KSTR + px] = vl;
        }
        // ---- B build: [oc][k], oc>=27 zero
#pragma unroll
        for (int i2 = 0; i2 < 8; i2++) {
            const int idx = tid + i2*256;
            const int oc = idx >> 6, kr = idx & 63;
            __nv_bfloat16 vh = __float2bfloat16(0.f), vl = vh;
            if (oc < OC) {
                const int gi = oc*CK + c*64 + kr;
                vh = g_oh[gi]; vl = g_ol[gi];
            }
            s_bh[oc*72 + kr] = vh;
            s_bl[oc*72 + kr] = vl;
        }
        __syncthreads();

        // ---- prefetch next chunk into regs (LDGs overlap MMA below)
        if (c < 8) im2col_fetch(xb, row, px, kr0, c+1, v);

        // ---- MMA: 4 ksteps of 16
#pragma unroll
        for (int ks = 0; ks < 4; ks++) {
            const uint32_t ao = (uint32_t)(ks * 16 * KSTR * 2);
            const uint32_t bo = (uint32_t)(ks * 32);
            uint32_t ah[4], al[4], bh[2][4], bl[2][4];
            ldsm_x4_t(ah, sb_ah + a_lane + ao);
            ldsm_x4_t(al, sb_al + a_lane + ao);
            ldsm_x4(bh[0], sb_bh + b_lane + bo);
            ldsm_x4(bh[1], sb_bh + b_lane + 16*72*2 + bo);
            ldsm_x4(bl[0], sb_bl + b_lane + bo);
            ldsm_x4(bl[1], sb_bl + b_lane + 16*72*2 + bo);
#pragma unroll
            for (int n = 0; n < 4; n++) {
                const uint32_t* bhp = &bh[n>>1][(n&1)*2];
                const uint32_t* blp = &bl[n>>1][(n&1)*2];
                mma_bf16(acc[n], ah, bhp);
                mma_bf16(acc[n], ah, blp);
                mma_bf16(acc[n], al, bhp);
            }
        }
        __syncthreads();
    }

    // ---- stage results [px][oc] (stride 33) in smem (aliases A)
    float* s_out = (float*)(smem + S1_A);
#pragma unroll
    for (int n = 0; n < 4; n++) {
#pragma unroll
        for (int q = 0; q < 4; q++) {
            const int pr = wid*16 + (lane >> 2) + 8*(q >> 1);
            const int oc = n*8 + (lane & 3)*2 + (q & 1);
            s_out[pr*33 + oc] = acc[n][q];
        }
    }
    __syncthreads();

    // ---- epilogue: corner weights + packed indices per (k, px)
    for (int i = tid; i < KT*128; i += 256) {
        const int k = i >> 7, p = i & 127;
        const float oy = s_out[p*33 + k]      + __ldg(&bofs[k]);
        const float ox = s_out[p*33 + 9 + k]  + __ldg(&bofs[9 + k]);
        const float z  = s_out[p*33 + 18 + k] + __ldg(&bofs[18 + k]);
        const float mv = 1.f / (1.f + __expf(-z));
        const float py  = oy + (float)(row - 1 + k/3);
        const float pxx = ox + (float)(p   - 1 + k%3);
        const float y0f = floorf(py), x0f = floorf(pxx);
        const float dy = py - y0f, dx = pxx - x0f;
        const int y0 = (int)y0f, x0 = (int)x0f, y1 = y0+1, x1 = x0+1;
        const bool vy0 = (y0>=0)&(y0<HH), vy1 = (y1>=0)&(y1<HH);
        const bool vx0 = (x0>=0)&(x0<WW), vx1 = (x1>=0)&(x1<WW);
        const int cy0 = min(max(y0,0),HH-1), cy1 = min(max(y1,0),HH-1);
        const int cx0 = min(max(x0,0),WW-1), cx1 = min(max(x1,0),WW-1);
        float4 wq;
        wq.x = (1.f-dy)*(1.f-dx)*mv * (float)(vy0&vx0);
        wq.y = (1.f-dy)*dx      *mv * (float)(vy0&vx1);
        wq.z = dy*(1.f-dx)      *mv * (float)(vy1&vx0);
        wq.w = dy*dx            *mv * (float)(vy1&vx1);
        const int o = ((b*KT + k)*HH + row)*WW + p;
        g_w4[o]  = wq;
        g_idx[o] = (uint32_t)cy0 | ((uint32_t)cx0<<8) | ((uint32_t)cy1<<16) | ((uint32_t)cx1<<24);
    }
}

// ---------------------------------------------------------------------------
// Kernel 2: gather -> bf16x3 mma.sync GEMM, software-pipelined:
// bilinear gather of chunk c+1 into regs overlaps MMA(c).
// ---------------------------------------------------------------------------
#define SO_W4   0                          // 9*128 float4 = 18432
#define SO_IDX  18432                      // 9*128 u32    = 4608
#define SO_A    23040                      // A hi: 64*136*2 = 17408
#define SO_AL   (SO_A  + 64*KSTR*2)
#define SO_B    (SO_AL + 64*KSTR*2)        // B hi 64*72*2 = 9216
#define SO_BL   (SO_B  + 9216)
#define K2_SMEM (SO_BL + 9216)             // 76288 -> 2 blocks/SM
#define EP_FLOATS (32*33)

__device__ __forceinline__ void gather_fetch(
    const float* __restrict__ xb, const float* __restrict__ s_w4,
    const uint32_t* __restrict__ s_idx, int c, int gk0, int gpx, float* v)
{
#pragma unroll
    for (int i2 = 0; i2 < 32; i2++) {
        const int kr = gk0 + i2*2;
        const int kg = c*64 + kr;
        const int ch = kg / 9;
        const int tp = kg - ch*9;
        const float* xc = xb + ch * HW;
        const int e = tp*128 + gpx;
        const float4 wq = *(const float4*)(s_w4 + e*4);
        const uint32_t pi = s_idx[e];
        const int cy0 = pi & 255, cx0 = (pi>>8)&255, cy1 = (pi>>16)&255, cx1 = pi>>24;
        v[i2] = wq.x*__ldg(&xc[cy0*WW+cx0]) + wq.y*__ldg(&xc[cy0*WW+cx1])
              + wq.z*__ldg(&xc[cy1*WW+cx0]) + wq.w*__ldg(&xc[cy1*WW+cx1]);
    }
}

__global__ void __launch_bounds__(256, 2) dcn_mma_kernel(
    const float* __restrict__ x,
    const float* __restrict__ bdcn,
    float* __restrict__ out)
{
    extern __shared__ char smem[];
    float*    s_w4  = (float*)(smem + SO_W4);
    uint32_t* s_idx = (uint32_t*)(smem + SO_IDX);

    const int tid  = threadIdx.x;
    const int wid  = tid >> 5;
    const int lane = tid & 31;
    const int b    = blockIdx.x >> 7;
    const int row  = blockIdx.x & 127;

    // ---- prepass: copy precomputed corner weights + indices
    {
        const int gbase = (b*KT*HH + row)*WW;
        for (int i = tid; i < KT*128; i += 256) {
            const int k = i >> 7, p = i & 127;
            const int o = gbase + k*HW + p;
            *(float4*)(s_w4 + i*4) = g_w4[o];
            s_idx[i] = g_idx[o];
        }
    }
    __syncthreads();

    const int wm  = wid >> 1;
    const int wn  = wid & 1;
    const int px0 = wm * 32;
    const int co0 = wn * 32;

    const uint32_t sb_ah = smem_to_u32(smem + SO_A);
    const uint32_t sb_al = smem_to_u32(smem + SO_AL);
    const uint32_t sb_bh = smem_to_u32(smem + SO_B);
    const uint32_t sb_bl = smem_to_u32(smem + SO_BL);

    const int aj = lane >> 3;
    const uint32_t a_lane = (uint32_t)((((aj >> 1) * 8 + (lane & 7)) * KSTR
                                        + px0 + (aj & 1) * 8) * 2);
    const uint32_t b_lane = (uint32_t)(((co0 + ((lane >> 4) & 1) * 8 + (lane & 7)) * 72
                                        + ((lane >> 3) & 1) * 8) * 2);

    float acc[2][4][4];
#pragma unroll
    for (int m = 0; m < 2; m++)
#pragma unroll
        for (int n = 0; n < 4; n++)
#pragma unroll
            for (int q = 0; q < 4; q++) acc[m][n][q] = 0.f;

    const float* xb = x + (size_t)b * CC * HW;
    __nv_bfloat16* s_ah = (__nv_bfloat16*)(smem + SO_A);
    __nv_bfloat16* s_al = (__nv_bfloat16*)(smem + SO_AL);
    __nv_bfloat16* s_bh = (__nv_bfloat16*)(smem + SO_B);
    __nv_bfloat16* s_bl = (__nv_bfloat16*)(smem + SO_BL);

    const int gpx = tid & 127;
    const int gk0 = tid >> 7;

    float v[32];
    gather_fetch(xb, s_w4, s_idx, 0, gk0, gpx, v);

    for (int c = 0; c < 9; c++) {
        // ---- store prefetched A chunk (hi/lo)
#pragma unroll
        for (int i2 = 0; i2 < 32; i2++) {
            const int kr = gk0 + i2*2;
            __nv_bfloat16 vh, vl; bf16split(v[i2], vh, vl);
            s_ah[kr*KSTR + gpx] = vh;
            s_al[kr*KSTR + gpx] = vl;
        }
        // ---- stage B chunk (weights hi/lo), [co][k]
#pragma unroll
        for (int i2 = 0; i2 < 16; i2++) {
            const int idx = tid + i2*256;
            const int co = idx >> 6, kr = idx & 63;
            const int gi = co*CK + c*64 + kr;
            s_bh[co*72 + kr] = g_wh[gi];
            s_bl[co*72 + kr] = g_wl[gi];
        }
        __syncthreads();

        // ---- prefetch next chunk (LDGs drain during MMA below)
        if (c < 8) gather_fetch(xb, s_w4, s_idx, c+1, gk0, gpx, v);

        // ---- warp MMAs: 4 k-steps of 16
#pragma unroll
        for (int ks = 0; ks < 4; ks++) {
            const uint32_t ao = (uint32_t)(ks * 16 * KSTR * 2);
            const uint32_t bo = (uint32_t)(ks * 32);
            uint32_t ah[2][4], al[2][4], bh[2][4], bl[2][4];
            ldsm_x4_t(ah[0], sb_ah + a_lane + ao);
            ldsm_x4_t(ah[1], sb_ah + a_lane + ao + 32);
            ldsm_x4_t(al[0], sb_al + a_lane + ao);
            ldsm_x4_t(al[1], sb_al + a_lane + ao + 32);
            ldsm_x4(bh[0], sb_bh + b_lane + bo);
            ldsm_x4(bh[1], sb_bh + b_lane + 16*72*2 + bo);
            ldsm_x4(bl[0], sb_bl + b_lane + bo);
            ldsm_x4(bl[1], sb_bl + b_lane + 16*72*2 + bo);
#pragma unroll
            for (int m = 0; m < 2; m++) {
#pragma unroll
                for (int n = 0; n < 4; n++) {
                    const uint32_t* bhp = &bh[n>>1][(n&1)*2];
                    const uint32_t* blp = &bl[n>>1][(n&1)*2];
                    mma_bf16(acc[m][n], ah[m], bhp);
                    mma_bf16(acc[m][n], ah[m], blp);
                    mma_bf16(acc[m][n], al[m], bhp);
                }
            }
        }
        __syncthreads();
    }

    // ---- epilogue: per-warp transpose through smem (aliases A region)
    float* s_ep = (float*)(smem + SO_A) + wid * EP_FLOATS;
#pragma unroll
    for (int m = 0; m < 2; m++) {
#pragma unroll
        for (int n = 0; n < 4; n++) {
            const int pxl = m*16 + (lane >> 2);
            const int col = n*8 + (lane & 3)*2;
            s_ep[ col     *33 + pxl    ] = acc[m][n][0];
            s_ep[(col + 1)*33 + pxl    ] = acc[m][n][1];
            s_ep[ col     *33 + pxl + 8] = acc[m][n][2];
            s_ep[(col + 1)*33 + pxl + 8] = acc[m][n][3];
        }
    }
    __syncwarp();

    float* ob = out + (size_t)b*CO*HW + row*WW + px0;
#pragma unroll
    for (int col = 0; col < 32; col++) {
        const int co = co0 + col;
        ob[(size_t)co*HW + lane] = s_ep[col*33 + lane] + __ldg(&bdcn[co]);
    }
}

// ---------------------------------------------------------------------------
extern "C" void kernel_launch(void* const* d_in, const int* in_sizes, int n_in,
                              void* d_out, int out_size)
{
    const float* x        = (const float*)d_in[0];
    const float* w_offset = (const float*)d_in[1];
    const float* b_offset = (const float*)d_in[2];
    const float* w_dcn    = (const float*)d_in[3];
    const float* b_dcn    = (const float*)d_in[4];
    float* out = (float*)d_out;

    cudaFuncSetAttribute(offset_mma_kernel,
                         cudaFuncAttributeMaxDynamicSharedMemorySize, K1_SMEM);
    cudaFuncSetAttribute(dcn_mma_kernel,
                         cudaFuncAttributeMaxDynamicSharedMemorySize, K2_SMEM);

    wprep_kernel<<<(WPN + 255)/256, 256>>>(w_dcn, w_offset);
    offset_mma_kernel<<<BB*HH, 256, K1_SMEM>>>(x, b_offset);
    dcn_mma_kernel<<<BB*HH, 256, K2_SMEM>>>(x, b_dcn, out);
}